// round 1
// baseline (speedup 1.0000x reference)
#include <cuda_runtime.h>
#include <cstdint>

#define N_NODES 50000
#define N_EDGES 640000
#define IN_F    128
#define OUT_F   32
#define HEADS   4
#define ALPHA   0.2f

// ---------------- scratch (device globals; no allocation allowed) ----------------
__device__ float    g_Wh[N_NODES * 128];     // [N,128] transformed nodes
__device__ float    g_s[N_NODES * 8];        // [N][0..3]=s_src, [4..7]=s_dst
__device__ float    g_ve[HEADS * 128];       // [h][k] collapsed edge projection
__device__ float    g_p[N_EDGES * 4];        // [E][4] logits -> exp values
__device__ unsigned g_max[4];                // encoded per-head max
__device__ float    g_sum[4];                // per-head exp sum

// ordered-uint encoding for float atomicMax
__device__ __forceinline__ unsigned fenc(float f) {
    unsigned u = __float_as_uint(f);
    return (u & 0x80000000u) ? ~u : (u | 0x80000000u);
}
__device__ __forceinline__ float fdec(unsigned u) {
    return (u & 0x80000000u) ? __uint_as_float(u & 0x7fffffffu)
                             : __uint_as_float(~u);
}

// ---------------- K0: v_edge precompute + state reset ----------------
__global__ void k0_prep(const float* __restrict__ We, const float* __restrict__ a_edge) {
    int t = threadIdx.x;                  // 512 threads
    if (t < 4) { g_max[t] = 0u; g_sum[t] = 0.0f; }
    int k = t >> 2, h = t & 3;
    float s = 0.0f;
#pragma unroll
    for (int d = 0; d < 32; d++)
        s += We[k * 128 + h * 32 + d] * a_edge[h * 32 + d];
    g_ve[h * 128 + k] = s;                // [h][k] layout (conflict-free LDS.128 later)
}

// ---------------- K1: Wh = h @ W  (smem-tiled fp32) ----------------
// block=256 (8 warps), 32 nodes/block. Two k-passes of 64. Warp = 4 nodes,
// lane = 4 consecutive output cols (float4). FMA-issue bound ~48us.
__global__ __launch_bounds__(256) void k1_gemm(const float* __restrict__ h,
                                               const float* __restrict__ W) {
    __shared__ float Ws[64 * 128];        // 32KB
    __shared__ float hs[32 * 64];         // 8KB
    int tid = threadIdx.x, lane = tid & 31, w = tid >> 5;
    int nodeBase = blockIdx.x * 32;
    int n0 = nodeBase + w * 4;

    float4 acc0 = {0,0,0,0}, acc1 = {0,0,0,0}, acc2 = {0,0,0,0}, acc3 = {0,0,0,0};

    for (int pass = 0; pass < 2; pass++) {
        int kbase = pass * 64;
        // load W tile [64][128] as float4
        const float4* Wg4 = reinterpret_cast<const float4*>(W + kbase * 128);
        float4* Ws4w = reinterpret_cast<float4*>(Ws);
        for (int i = tid; i < 64 * 32; i += 256) Ws4w[i] = Wg4[i];
        // load h tile [32 nodes][64 k]
        for (int i = tid; i < 32 * 64; i += 256) {
            int nn = i >> 6, kk = i & 63;
            int n = nodeBase + nn;
            hs[i] = (n < N_NODES) ? h[n * 128 + kbase + kk] : 0.0f;
        }
        __syncthreads();

        const float4* Ws4 = reinterpret_cast<const float4*>(Ws);
        const float* h0p = &hs[(w * 4 + 0) * 64];
        const float* h1p = &hs[(w * 4 + 1) * 64];
        const float* h2p = &hs[(w * 4 + 2) * 64];
        const float* h3p = &hs[(w * 4 + 3) * 64];
#pragma unroll 8
        for (int kk = 0; kk < 64; kk++) {
            float4 wv = Ws4[kk * 32 + lane];
            float h0 = h0p[kk], h1 = h1p[kk], h2 = h2p[kk], h3 = h3p[kk];
            acc0.x += h0 * wv.x; acc0.y += h0 * wv.y; acc0.z += h0 * wv.z; acc0.w += h0 * wv.w;
            acc1.x += h1 * wv.x; acc1.y += h1 * wv.y; acc1.z += h1 * wv.z; acc1.w += h1 * wv.w;
            acc2.x += h2 * wv.x; acc2.y += h2 * wv.y; acc2.z += h2 * wv.z; acc2.w += h2 * wv.w;
            acc3.x += h3 * wv.x; acc3.y += h3 * wv.y; acc3.z += h3 * wv.z; acc3.w += h3 * wv.w;
        }
        __syncthreads();
    }
    float4* Wh4 = reinterpret_cast<float4*>(g_Wh);
    if (n0 + 0 < N_NODES) Wh4[(size_t)(n0 + 0) * 32 + lane] = acc0;
    if (n0 + 1 < N_NODES) Wh4[(size_t)(n0 + 1) * 32 + lane] = acc1;
    if (n0 + 2 < N_NODES) Wh4[(size_t)(n0 + 2) * 32 + lane] = acc2;
    if (n0 + 3 < N_NODES) Wh4[(size_t)(n0 + 3) * 32 + lane] = acc3;
}

// ---------------- K1b: per-node attention scalars ----------------
// warp per node: s_src[n,h] = Wh[n,h,:]·a_src[h], s_dst likewise.
__global__ __launch_bounds__(256) void k1b_scal(const float* __restrict__ a_src,
                                                const float* __restrict__ a_dst) {
    __shared__ float as[128], ad[128];
    int tid = threadIdx.x;
    if (tid < 128) { as[tid] = a_src[tid]; ad[tid] = a_dst[tid]; }
    __syncthreads();
    int warp = (blockIdx.x * 256 + tid) >> 5;
    int lane = tid & 31;
    if (warp >= N_NODES) return;
    float4 v = reinterpret_cast<const float4*>(g_Wh)[(size_t)warp * 32 + lane];
    int c = 4 * lane;                              // flat col == flat [h][d] index of a
    float ps = v.x * as[c] + v.y * as[c + 1] + v.z * as[c + 2] + v.w * as[c + 3];
    float pd = v.x * ad[c] + v.y * ad[c + 1] + v.z * ad[c + 2] + v.w * ad[c + 3];
    // reduce within 8-lane head groups
    ps += __shfl_xor_sync(0xffffffffu, ps, 1); pd += __shfl_xor_sync(0xffffffffu, pd, 1);
    ps += __shfl_xor_sync(0xffffffffu, ps, 2); pd += __shfl_xor_sync(0xffffffffu, pd, 2);
    ps += __shfl_xor_sync(0xffffffffu, ps, 4); pd += __shfl_xor_sync(0xffffffffu, pd, 4);
    if ((lane & 7) == 0) {
        int head = lane >> 3;
        g_s[warp * 8 + head]     = ps;
        g_s[warp * 8 + 4 + head] = pd;
    }
}

// ---------------- K2: edge logits + leakyrelu + global max ----------------
// warp per edge, streams edge_feat (327MB) once. DRAM-bound (~55us predicted).
__global__ __launch_bounds__(256) void k2_logits(const float* __restrict__ ef,
                                                 const int* __restrict__ ei) {
    __shared__ float ve[512];
    __shared__ unsigned bmax[4];
    int tid = threadIdx.x;
    if (tid < 4) bmax[tid] = 0u;
    for (int i = tid; i < 512; i += 256) ve[i] = g_ve[i];
    __syncthreads();

    int e = blockIdx.x * 8 + (tid >> 5);
    int lane = tid & 31;
    if (e < N_EDGES) {
        float4 x = reinterpret_cast<const float4*>(ef)[(size_t)e * 32 + lane];
        const float4* ve4 = reinterpret_cast<const float4*>(ve);
        float4 v0 = ve4[0 * 32 + lane];
        float4 v1 = ve4[1 * 32 + lane];
        float4 v2 = ve4[2 * 32 + lane];
        float4 v3 = ve4[3 * 32 + lane];
        float p0 = x.x * v0.x + x.y * v0.y + x.z * v0.z + x.w * v0.w;
        float p1 = x.x * v1.x + x.y * v1.y + x.z * v1.z + x.w * v1.w;
        float p2 = x.x * v2.x + x.y * v2.y + x.z * v2.z + x.w * v2.w;
        float p3 = x.x * v3.x + x.y * v3.y + x.z * v3.z + x.w * v3.w;
#pragma unroll
        for (int m = 16; m; m >>= 1) {
            p0 += __shfl_xor_sync(0xffffffffu, p0, m);
            p1 += __shfl_xor_sync(0xffffffffu, p1, m);
            p2 += __shfl_xor_sync(0xffffffffu, p2, m);
            p3 += __shfl_xor_sync(0xffffffffu, p3, m);
        }
        if (lane == 0) {
            int src = ei[e], dst = ei[N_EDGES + e];
            float4 ss = *reinterpret_cast<const float4*>(g_s + (size_t)src * 8);
            float4 sd = *reinterpret_cast<const float4*>(g_s + (size_t)dst * 8 + 4);
            float4 ev;
            ev.x = p0 + ss.x + sd.x; ev.y = p1 + ss.y + sd.y;
            ev.z = p2 + ss.z + sd.z; ev.w = p3 + ss.w + sd.w;
            ev.x = (ev.x >= 0.f) ? ev.x : ALPHA * ev.x;
            ev.y = (ev.y >= 0.f) ? ev.y : ALPHA * ev.y;
            ev.z = (ev.z >= 0.f) ? ev.z : ALPHA * ev.z;
            ev.w = (ev.w >= 0.f) ? ev.w : ALPHA * ev.w;
            reinterpret_cast<float4*>(g_p)[e] = ev;
            atomicMax(&bmax[0], fenc(ev.x));
            atomicMax(&bmax[1], fenc(ev.y));
            atomicMax(&bmax[2], fenc(ev.z));
            atomicMax(&bmax[3], fenc(ev.w));
        }
    }
    __syncthreads();
    if (tid < 4) atomicMax(&g_max[tid], bmax[tid]);
}

// ---------------- K3: exp(e - max), global sums ----------------
__global__ __launch_bounds__(256) void k3_exp() {
    __shared__ float bs[4];
    int tid = threadIdx.x;
    if (tid < 4) bs[tid] = 0.0f;
    __syncthreads();
    int e = blockIdx.x * 256 + tid;
    int lane = tid & 31;
    float m0 = fdec(g_max[0]), m1 = fdec(g_max[1]), m2 = fdec(g_max[2]), m3 = fdec(g_max[3]);
    float4 v = {0,0,0,0};
    if (e < N_EDGES) {
        v = reinterpret_cast<float4*>(g_p)[e];
        v.x = __expf(v.x - m0); v.y = __expf(v.y - m1);
        v.z = __expf(v.z - m2); v.w = __expf(v.w - m3);
        reinterpret_cast<float4*>(g_p)[e] = v;
    }
#pragma unroll
    for (int m = 16; m; m >>= 1) {
        v.x += __shfl_xor_sync(0xffffffffu, v.x, m);
        v.y += __shfl_xor_sync(0xffffffffu, v.y, m);
        v.z += __shfl_xor_sync(0xffffffffu, v.z, m);
        v.w += __shfl_xor_sync(0xffffffffu, v.w, m);
    }
    if (lane == 0) {
        atomicAdd(&bs[0], v.x); atomicAdd(&bs[1], v.y);
        atomicAdd(&bs[2], v.z); atomicAdd(&bs[3], v.w);
    }
    __syncthreads();
    if (tid < 4) atomicAdd(&g_sum[tid], bs[tid]);
}

// ---------------- K4: normalize + gather Wh[src] + scatter-add to out[dst] ----------------
// warp per edge; Wh and out are both L2-resident (25.6MB each).
__global__ __launch_bounds__(256) void k4_scatter(const int* __restrict__ ei,
                                                  float* __restrict__ out) {
    int e = blockIdx.x * 8 + (threadIdx.x >> 5);
    int lane = threadIdx.x & 31;
    if (e >= N_EDGES) return;
    int src = ei[e], dst = ei[N_EDGES + e];
    int head = lane >> 3;
    float pv = __ldg(&g_p[(size_t)e * 4 + head]);
    float s  = __ldg(&g_sum[head]);
    float scale = __fdividef(pv, s);
    float4 wv = reinterpret_cast<const float4*>(g_Wh)[(size_t)src * 32 + lane];
    float4 m;
    m.x = wv.x * scale; m.y = wv.y * scale; m.z = wv.z * scale; m.w = wv.w * scale;
    float* dstp = out + (size_t)dst * 128 + 4 * lane;
    asm volatile("red.global.add.v4.f32 [%0], {%1,%2,%3,%4};"
                 :: "l"(dstp), "f"(m.x), "f"(m.y), "f"(m.z), "f"(m.w)
                 : "memory");
}

// ---------------- K5: relu ----------------
__global__ __launch_bounds__(256) void k5_relu(float* __restrict__ out) {
    int i = blockIdx.x * 256 + threadIdx.x;
    if (i < N_NODES * 128 / 4) {
        float4 v = reinterpret_cast<float4*>(out)[i];
        v.x = fmaxf(v.x, 0.f); v.y = fmaxf(v.y, 0.f);
        v.z = fmaxf(v.z, 0.f); v.w = fmaxf(v.w, 0.f);
        reinterpret_cast<float4*>(out)[i] = v;
    }
}

extern "C" void kernel_launch(void* const* d_in, const int* in_sizes, int n_in,
                              void* d_out, int out_size) {
    const int*   ei     = (const int*)d_in[0];   // [2,E]
    const float* h      = (const float*)d_in[1]; // [N,128]
    const float* ef     = (const float*)d_in[2]; // [E,128]
    const float* W      = (const float*)d_in[3]; // [128,128]
    const float* We     = (const float*)d_in[4]; // [128,128]
    const float* a_src  = (const float*)d_in[5]; // [1,4,32]
    const float* a_dst  = (const float*)d_in[6];
    const float* a_edge = (const float*)d_in[7];
    float* out = (float*)d_out;

    cudaMemsetAsync(out, 0, (size_t)out_size * sizeof(float), 0);

    k0_prep<<<1, 512>>>(We, a_edge);
    k1_gemm<<<(N_NODES + 31) / 32, 256>>>(h, W);
    k1b_scal<<<(N_NODES * 32 + 255) / 256, 256>>>(a_src, a_dst);
    k2_logits<<<(N_EDGES + 7) / 8, 256>>>(ef, ei);
    k3_exp<<<(N_EDGES + 255) / 256, 256>>>();
    k4_scatter<<<(N_EDGES + 7) / 8, 256>>>(ei, out);
    k5_relu<<<(N_NODES * 128 / 4 + 255) / 256, 256>>>(out);
}

// round 2
// speedup vs baseline: 1.1904x; 1.1904x over previous
#include <cuda_runtime.h>
#include <cstdint>

#define N_NODES 50000
#define N_EDGES 640000
#define IN_F    128
#define OUT_F   32
#define HEADS   4
#define ALPHA   0.2f

// ---------------- scratch (device globals; no allocation allowed) ----------------
__device__ float    g_Wh[N_NODES * 128];     // [N,128] transformed nodes
__device__ float    g_s[N_NODES * 8];        // [N][0..3]=s_src, [4..7]=s_dst
__device__ float    g_ve[HEADS * 128];       // [h][k] collapsed edge projection
__device__ float    g_p[N_EDGES * 4];        // [E][4] logits -> exp values
__device__ unsigned g_max[4];                // encoded per-head max
__device__ float    g_sum[4];                // per-head exp sum
// CSR scratch
__device__ int      g_cnt[N_NODES];          // counts -> cursors -> (after fill) row ends
__device__ int      g_off[N_NODES];          // row starts
__device__ int      g_list[N_EDGES];         // edge ids grouped by dst
__device__ int      g_bsum[256];             // scan block sums

// ordered-uint encoding for float atomicMax
__device__ __forceinline__ unsigned fenc(float f) {
    unsigned u = __float_as_uint(f);
    return (u & 0x80000000u) ? ~u : (u | 0x80000000u);
}
__device__ __forceinline__ float fdec(unsigned u) {
    return (u & 0x80000000u) ? __uint_as_float(u & 0x7fffffffu)
                             : __uint_as_float(~u);
}

__device__ __forceinline__ unsigned long long packf2(float v) {
    unsigned long long r;
    asm("mov.b64 %0, {%1, %1};" : "=l"(r) : "f"(v));
    return r;
}

// ---------------- K_init: zero counts + v_edge precompute + state reset --------
__global__ void k_init(const float* __restrict__ We, const float* __restrict__ a_edge) {
    int t = threadIdx.x;
    int gid = blockIdx.x * 256 + t;
    if (gid < N_NODES) g_cnt[gid] = 0;
    if (gid < 4) { g_max[gid] = 0u; g_sum[gid] = 0.0f; }
    if (blockIdx.x < 2) {
        int idx = blockIdx.x * 256 + t;       // 0..511
        int k = idx >> 2, h = idx & 3;
        float s = 0.0f;
#pragma unroll
        for (int d = 0; d < 32; d++)
            s += We[k * 128 + h * 32 + d] * a_edge[h * 32 + d];
        g_ve[h * 128 + k] = s;                // [h][k]
    }
}

// ---------------- K1: Wh = h @ W  (smem-tiled, packed f32x2 FMA) ----------------
__global__ __launch_bounds__(256) void k1_gemm(const float* __restrict__ h,
                                               const float* __restrict__ W) {
    __shared__ float Ws[64 * 128];                 // 32KB
    __shared__ unsigned long long hs2[32 * 64];    // 16KB, pre-packed {h,h}
    int tid = threadIdx.x, lane = tid & 31, w = tid >> 5;
    int nodeBase = blockIdx.x * 32;

    unsigned long long a0x = 0, a0z = 0, a1x = 0, a1z = 0,
                       a2x = 0, a2z = 0, a3x = 0, a3z = 0;

    for (int pass = 0; pass < 2; pass++) {
        int kbase = pass * 64;
        const float4* Wg4 = reinterpret_cast<const float4*>(W + kbase * 128);
        float4* Ws4w = reinterpret_cast<float4*>(Ws);
        for (int i = tid; i < 64 * 32; i += 256) Ws4w[i] = Wg4[i];
        for (int i = tid; i < 32 * 64; i += 256) {
            int nn = i >> 6, kk = i & 63;
            int n = nodeBase + nn;
            float v = (n < N_NODES) ? h[(size_t)n * 128 + kbase + kk] : 0.0f;
            hs2[i] = packf2(v);
        }
        __syncthreads();

        const ulonglong2* W2 = reinterpret_cast<const ulonglong2*>(Ws);
        const unsigned long long* h0p = &hs2[(w * 4 + 0) * 64];
        const unsigned long long* h1p = &hs2[(w * 4 + 1) * 64];
        const unsigned long long* h2p = &hs2[(w * 4 + 2) * 64];
        const unsigned long long* h3p = &hs2[(w * 4 + 3) * 64];
#pragma unroll 16
        for (int kk = 0; kk < 64; kk++) {
            ulonglong2 wv = W2[kk * 32 + lane];
            unsigned long long b0 = h0p[kk], b1 = h1p[kk], b2 = h2p[kk], b3 = h3p[kk];
            asm("fma.rn.f32x2 %0,%1,%2,%0;" : "+l"(a0x) : "l"(b0), "l"(wv.x));
            asm("fma.rn.f32x2 %0,%1,%2,%0;" : "+l"(a0z) : "l"(b0), "l"(wv.y));
            asm("fma.rn.f32x2 %0,%1,%2,%0;" : "+l"(a1x) : "l"(b1), "l"(wv.x));
            asm("fma.rn.f32x2 %0,%1,%2,%0;" : "+l"(a1z) : "l"(b1), "l"(wv.y));
            asm("fma.rn.f32x2 %0,%1,%2,%0;" : "+l"(a2x) : "l"(b2), "l"(wv.x));
            asm("fma.rn.f32x2 %0,%1,%2,%0;" : "+l"(a2z) : "l"(b2), "l"(wv.y));
            asm("fma.rn.f32x2 %0,%1,%2,%0;" : "+l"(a3x) : "l"(b3), "l"(wv.x));
            asm("fma.rn.f32x2 %0,%1,%2,%0;" : "+l"(a3z) : "l"(b3), "l"(wv.y));
        }
        __syncthreads();
    }

    int n0 = nodeBase + w * 4;
    float4* Wh4 = reinterpret_cast<float4*>(g_Wh);
#define UNPK(X, Z) make_float4(__uint_as_float((unsigned)(X)), __uint_as_float((unsigned)((X) >> 32)), \
                               __uint_as_float((unsigned)(Z)), __uint_as_float((unsigned)((Z) >> 32)))
    if (n0 + 0 < N_NODES) Wh4[(size_t)(n0 + 0) * 32 + lane] = UNPK(a0x, a0z);
    if (n0 + 1 < N_NODES) Wh4[(size_t)(n0 + 1) * 32 + lane] = UNPK(a1x, a1z);
    if (n0 + 2 < N_NODES) Wh4[(size_t)(n0 + 2) * 32 + lane] = UNPK(a2x, a2z);
    if (n0 + 3 < N_NODES) Wh4[(size_t)(n0 + 3) * 32 + lane] = UNPK(a3x, a3z);
#undef UNPK
}

// ---------------- K1b: per-node attention scalars ----------------
__global__ __launch_bounds__(256) void k1b_scal(const float* __restrict__ a_src,
                                                const float* __restrict__ a_dst) {
    __shared__ float as[128], ad[128];
    int tid = threadIdx.x;
    if (tid < 128) { as[tid] = a_src[tid]; ad[tid] = a_dst[tid]; }
    __syncthreads();
    int warp = (blockIdx.x * 256 + tid) >> 5;
    int lane = tid & 31;
    if (warp >= N_NODES) return;
    float4 v = reinterpret_cast<const float4*>(g_Wh)[(size_t)warp * 32 + lane];
    int c = 4 * lane;
    float ps = v.x * as[c] + v.y * as[c + 1] + v.z * as[c + 2] + v.w * as[c + 3];
    float pd = v.x * ad[c] + v.y * ad[c + 1] + v.z * ad[c + 2] + v.w * ad[c + 3];
    ps += __shfl_xor_sync(0xffffffffu, ps, 1); pd += __shfl_xor_sync(0xffffffffu, pd, 1);
    ps += __shfl_xor_sync(0xffffffffu, ps, 2); pd += __shfl_xor_sync(0xffffffffu, pd, 2);
    ps += __shfl_xor_sync(0xffffffffu, ps, 4); pd += __shfl_xor_sync(0xffffffffu, pd, 4);
    if ((lane & 7) == 0) {
        int head = lane >> 3;
        g_s[warp * 8 + head]     = ps;
        g_s[warp * 8 + 4 + head] = pd;
    }
}

// ---------------- K2: edge logits (thread per edge-head, shuffle-free) -----------
// Block = 256 threads, 64 edges. Transposed smem tile [kc][edge] for conflict-free
// reads; each thread owns full dot for (edge, head). Also histograms dst counts.
__global__ __launch_bounds__(256) void k2_logits(const float4* __restrict__ ef4,
                                                 const int* __restrict__ ei) {
    __shared__ float4 xs[32][65];        // [kc][edge], padded: 33.3KB
    __shared__ float4 ves[4][33];        // [h][kc], padded
    __shared__ unsigned bmax[4];
    int tid = threadIdx.x;
    if (tid < 128) ves[tid >> 5][tid & 31] = reinterpret_cast<const float4*>(g_ve)[tid];
    if (tid < 4) bmax[tid] = 0u;

    int ebase = blockIdx.x * 64;         // grid = 10000 blocks, exact
    for (int i = tid; i < 64 * 32; i += 256) {
        int el = i >> 5, kc = i & 31;
        xs[kc][el] = ef4[(size_t)(ebase + el) * 32 + kc];
    }
    __syncthreads();

    int el = tid >> 2, h = tid & 3;
    unsigned long long accA = 0, accB = 0;
#pragma unroll
    for (int kc = 0; kc < 32; kc++) {
        ulonglong2 x2 = *reinterpret_cast<const ulonglong2*>(&xs[kc][el]);
        ulonglong2 v2 = *reinterpret_cast<const ulonglong2*>(&ves[h][kc]);
        asm("fma.rn.f32x2 %0,%1,%2,%0;" : "+l"(accA) : "l"(x2.x), "l"(v2.x));
        asm("fma.rn.f32x2 %0,%1,%2,%0;" : "+l"(accB) : "l"(x2.y), "l"(v2.y));
    }
    float p = __uint_as_float((unsigned)accA) + __uint_as_float((unsigned)(accA >> 32))
            + __uint_as_float((unsigned)accB) + __uint_as_float((unsigned)(accB >> 32));

    int e = ebase + el;
    int src = __ldg(&ei[e]);
    int dst = __ldg(&ei[N_EDGES + e]);
    float logit = p + __ldg(&g_s[(size_t)src * 8 + h]) + __ldg(&g_s[(size_t)dst * 8 + 4 + h]);
    logit = (logit >= 0.f) ? logit : ALPHA * logit;
    g_p[(size_t)e * 4 + h] = logit;             // index = ebase*4 + tid -> coalesced
    if (h == 0) atomicAdd(&g_cnt[dst], 1);      // histogram for CSR

    // per-head max: reduce over the 8 edges in this warp (lane strides of 4)
    float m = logit;
    m = fmaxf(m, __shfl_xor_sync(0xffffffffu, m, 4));
    m = fmaxf(m, __shfl_xor_sync(0xffffffffu, m, 8));
    m = fmaxf(m, __shfl_xor_sync(0xffffffffu, m, 16));
    int lane = tid & 31;
    if (lane < 4) atomicMax(&bmax[lane], fenc(m));
    __syncthreads();
    if (tid < 4) atomicMax(&g_max[tid], bmax[tid]);
}

// ---------------- scan (3 small kernels) ----------------
__global__ void k_scan1() {
    __shared__ int s[256];
    int t = threadIdx.x;
    int i = blockIdx.x * 256 + t;
    int c = (i < N_NODES) ? g_cnt[i] : 0;
    s[t] = c;
    __syncthreads();
#pragma unroll
    for (int d = 1; d < 256; d <<= 1) {
        int v = (t >= d) ? s[t - d] : 0;
        __syncthreads();
        s[t] += v;
        __syncthreads();
    }
    if (i < N_NODES) g_off[i] = s[t] - c;
    if (t == 255) g_bsum[blockIdx.x] = s[255];
}
__global__ void k_scan2(int nblocks) {
    __shared__ int s[256];
    int t = threadIdx.x;
    int c = (t < nblocks) ? g_bsum[t] : 0;
    s[t] = c;
    __syncthreads();
#pragma unroll
    for (int d = 1; d < 256; d <<= 1) {
        int v = (t >= d) ? s[t - d] : 0;
        __syncthreads();
        s[t] += v;
        __syncthreads();
    }
    if (t < nblocks) g_bsum[t] = s[t] - c;   // exclusive
}
__global__ void k_scan3() {
    int i = blockIdx.x * 256 + threadIdx.x;
    if (i < N_NODES) {
        int v = g_off[i] + g_bsum[blockIdx.x];
        g_off[i] = v;
        g_cnt[i] = v;                        // becomes fill cursor
    }
}

// ---------------- K3: exp(e-max) + sums + CSR fill ----------------
__global__ __launch_bounds__(256) void k3_exp_fill(const int* __restrict__ ei) {
    __shared__ float bs[4];
    int tid = threadIdx.x;
    if (tid < 4) bs[tid] = 0.0f;
    __syncthreads();
    int e = blockIdx.x * 256 + tid;          // grid 2500, exact
    int lane = tid & 31;
    float m0 = fdec(g_max[0]), m1 = fdec(g_max[1]), m2 = fdec(g_max[2]), m3 = fdec(g_max[3]);
    float4 v = reinterpret_cast<float4*>(g_p)[e];
    v.x = __expf(v.x - m0); v.y = __expf(v.y - m1);
    v.z = __expf(v.z - m2); v.w = __expf(v.w - m3);
    reinterpret_cast<float4*>(g_p)[e] = v;
    // CSR fill
    int dst = __ldg(&ei[N_EDGES + e]);
    int idx = atomicAdd(&g_cnt[dst], 1);
    g_list[idx] = e;
    // head sums
    float4 r = v;
#pragma unroll
    for (int m = 16; m; m >>= 1) {
        r.x += __shfl_xor_sync(0xffffffffu, r.x, m);
        r.y += __shfl_xor_sync(0xffffffffu, r.y, m);
        r.z += __shfl_xor_sync(0xffffffffu, r.z, m);
        r.w += __shfl_xor_sync(0xffffffffu, r.w, m);
    }
    if (lane == 0) {
        atomicAdd(&bs[0], r.x); atomicAdd(&bs[1], r.y);
        atomicAdd(&bs[2], r.z); atomicAdd(&bs[3], r.w);
    }
    __syncthreads();
    if (tid < 4) atomicAdd(&g_sum[tid], bs[tid]);
}

// ---------------- K4: warp-per-dst gather + fused ReLU ----------------
__global__ __launch_bounds__(256) void k4_gather(const int* __restrict__ ei,
                                                 float* __restrict__ out) {
    int node = (blockIdx.x * 256 + threadIdx.x) >> 5;
    int lane = threadIdx.x & 31;
    if (node >= N_NODES) return;
    int head = lane >> 3;
    float inv = __fdividef(1.0f, __ldg(&g_sum[head]));
    int beg = __ldg(&g_off[node]);
    int end = __ldg(&g_cnt[node]);           // cursor == row end after fill
    const float4* Wh4 = reinterpret_cast<const float4*>(g_Wh);
    const float4* p4  = reinterpret_cast<const float4*>(g_p);
    float4 acc = {0.f, 0.f, 0.f, 0.f};
    for (int i = beg; i < end; i++) {
        int e = __ldg(&g_list[i]);
        int src = __ldg(&ei[e]);
        float4 pv = __ldg(&p4[e]);
        float sc = (head == 0 ? pv.x : head == 1 ? pv.y : head == 2 ? pv.z : pv.w) * inv;
        float4 wv = __ldg(&Wh4[(size_t)src * 32 + lane]);
        acc.x = fmaf(sc, wv.x, acc.x);
        acc.y = fmaf(sc, wv.y, acc.y);
        acc.z = fmaf(sc, wv.z, acc.z);
        acc.w = fmaf(sc, wv.w, acc.w);
    }
    acc.x = fmaxf(acc.x, 0.f); acc.y = fmaxf(acc.y, 0.f);
    acc.z = fmaxf(acc.z, 0.f); acc.w = fmaxf(acc.w, 0.f);
    reinterpret_cast<float4*>(out)[(size_t)node * 32 + lane] = acc;
}

extern "C" void kernel_launch(void* const* d_in, const int* in_sizes, int n_in,
                              void* d_out, int out_size) {
    const int*   ei     = (const int*)d_in[0];   // [2,E]
    const float* h      = (const float*)d_in[1]; // [N,128]
    const float* ef     = (const float*)d_in[2]; // [E,128]
    const float* W      = (const float*)d_in[3]; // [128,128]
    const float* We     = (const float*)d_in[4]; // [128,128]
    const float* a_src  = (const float*)d_in[5]; // [1,4,32]
    const float* a_dst  = (const float*)d_in[6];
    const float* a_edge = (const float*)d_in[7];
    float* out = (float*)d_out;

    const int scan_blocks = (N_NODES + 255) / 256;   // 196

    k_init<<<scan_blocks, 256>>>(We, a_edge);
    k1_gemm<<<(N_NODES + 31) / 32, 256>>>(h, W);
    k1b_scal<<<(N_NODES * 32 + 255) / 256, 256>>>(a_src, a_dst);
    k2_logits<<<N_EDGES / 64, 256>>>((const float4*)ef, ei);
    k_scan1<<<scan_blocks, 256>>>();
    k_scan2<<<1, 256>>>(scan_blocks);
    k_scan3<<<scan_blocks, 256>>>();
    k3_exp_fill<<<N_EDGES / 256, 256>>>(ei);
    k4_gather<<<(N_NODES * 32 + 255) / 256, 256>>>(ei, out);
}

// round 3
// speedup vs baseline: 1.5179x; 1.2751x over previous
#include <cuda_runtime.h>
#include <cuda_fp16.h>
#include <cstdint>

#define N_NODES 50000
#define N_EDGES 640000
#define IN_F    128
#define OUT_F   32
#define HEADS   4
#define ALPHA   0.2f

// ---------------- scratch (device globals; no allocation allowed) ----------------
__device__ __half   g_Wh_h[N_NODES * 128];   // fp16 transformed nodes (only K4 reads)
__device__ float    g_s[N_NODES * 8];        // [N][0..3]=s_src, [4..7]=s_dst
__device__ float    g_ve[HEADS * 128];       // [h][k] collapsed edge projection
__device__ float    g_p[N_EDGES * 4];        // [E][4] logits -> exp values
__device__ unsigned g_max[4];                // encoded per-head max
__device__ float    g_sum[4];                // per-head exp sum
// CSR scratch
__device__ int      g_cnt[N_NODES];          // counts -> cursors (after fill: row ends)
__device__ int      g_off[N_NODES];          // row starts
__device__ int      g_list[N_EDGES];         // edge ids grouped by dst
__device__ int      g_bsum[256];             // scan block sums

__device__ __forceinline__ unsigned fenc(float f) {
    unsigned u = __float_as_uint(f);
    return (u & 0x80000000u) ? ~u : (u | 0x80000000u);
}
__device__ __forceinline__ float fdec(unsigned u) {
    return (u & 0x80000000u) ? __uint_as_float(u & 0x7fffffffu)
                             : __uint_as_float(~u);
}
__device__ __forceinline__ unsigned long long packf2(float v) {
    unsigned long long r;
    asm("mov.b64 %0, {%1, %1};" : "=l"(r) : "f"(v));
    return r;
}

// ---------------- K_init: zero counts + v_edge precompute + state reset --------
__global__ void k_init(const float* __restrict__ We, const float* __restrict__ a_edge) {
    int t = threadIdx.x;
    int gid = blockIdx.x * 256 + t;
    if (gid < N_NODES) g_cnt[gid] = 0;
    if (gid < 4) { g_max[gid] = 0u; g_sum[gid] = 0.0f; }
    if (blockIdx.x < 2) {
        int idx = blockIdx.x * 256 + t;       // 0..511
        int k = idx >> 2, h = idx & 3;
        float s = 0.0f;
#pragma unroll
        for (int d = 0; d < 32; d++)
            s += We[k * 128 + h * 32 + d] * a_edge[h * 32 + d];
        g_ve[h * 128 + k] = s;                // [h][k]
    }
}

// ---------------- K1: Wh = h @ W (f32x2 FMA) + fused per-node attention scalars --
__global__ __launch_bounds__(256) void k1_gemm(const float* __restrict__ h,
                                               const float* __restrict__ W,
                                               const float* __restrict__ a_src,
                                               const float* __restrict__ a_dst) {
    __shared__ float Ws[64 * 128];                 // 32KB
    __shared__ unsigned long long hs2[32 * 64];    // 16KB, pre-packed {h,h}
    __shared__ float as[128], ad[128];
    int tid = threadIdx.x, lane = tid & 31, w = tid >> 5;
    int nodeBase = blockIdx.x * 32;
    if (tid < 128) { as[tid] = a_src[tid]; ad[tid] = a_dst[tid]; }

    unsigned long long a0x = 0, a0z = 0, a1x = 0, a1z = 0,
                       a2x = 0, a2z = 0, a3x = 0, a3z = 0;

    for (int pass = 0; pass < 2; pass++) {
        int kbase = pass * 64;
        const float4* Wg4 = reinterpret_cast<const float4*>(W + kbase * 128);
        float4* Ws4w = reinterpret_cast<float4*>(Ws);
        for (int i = tid; i < 64 * 32; i += 256) Ws4w[i] = Wg4[i];
        for (int i = tid; i < 32 * 64; i += 256) {
            int nn = i >> 6, kk = i & 63;
            int n = nodeBase + nn;
            float v = (n < N_NODES) ? h[(size_t)n * 128 + kbase + kk] : 0.0f;
            hs2[i] = packf2(v);
        }
        __syncthreads();

        const ulonglong2* W2 = reinterpret_cast<const ulonglong2*>(Ws);
        const unsigned long long* h0p = &hs2[(w * 4 + 0) * 64];
        const unsigned long long* h1p = &hs2[(w * 4 + 1) * 64];
        const unsigned long long* h2p = &hs2[(w * 4 + 2) * 64];
        const unsigned long long* h3p = &hs2[(w * 4 + 3) * 64];
#pragma unroll 16
        for (int kk = 0; kk < 64; kk++) {
            ulonglong2 wv = W2[kk * 32 + lane];
            unsigned long long b0 = h0p[kk], b1 = h1p[kk], b2 = h2p[kk], b3 = h3p[kk];
            asm("fma.rn.f32x2 %0,%1,%2,%0;" : "+l"(a0x) : "l"(b0), "l"(wv.x));
            asm("fma.rn.f32x2 %0,%1,%2,%0;" : "+l"(a0z) : "l"(b0), "l"(wv.y));
            asm("fma.rn.f32x2 %0,%1,%2,%0;" : "+l"(a1x) : "l"(b1), "l"(wv.x));
            asm("fma.rn.f32x2 %0,%1,%2,%0;" : "+l"(a1z) : "l"(b1), "l"(wv.y));
            asm("fma.rn.f32x2 %0,%1,%2,%0;" : "+l"(a2x) : "l"(b2), "l"(wv.x));
            asm("fma.rn.f32x2 %0,%1,%2,%0;" : "+l"(a2z) : "l"(b2), "l"(wv.y));
            asm("fma.rn.f32x2 %0,%1,%2,%0;" : "+l"(a3x) : "l"(b3), "l"(wv.x));
            asm("fma.rn.f32x2 %0,%1,%2,%0;" : "+l"(a3z) : "l"(b3), "l"(wv.y));
        }
        __syncthreads();
    }

    int n0 = nodeBase + w * 4;
    uint2* Wh2 = reinterpret_cast<uint2*>(g_Wh_h);
    int c = 4 * lane;
    float asx = as[c], asy = as[c + 1], asz = as[c + 2], asw = as[c + 3];
    float adx = ad[c], ady = ad[c + 1], adz = ad[c + 2], adw = ad[c + 3];
#define UNPK(X, Z) make_float4(__uint_as_float((unsigned)(X)), __uint_as_float((unsigned)((X) >> 32)), \
                               __uint_as_float((unsigned)(Z)), __uint_as_float((unsigned)((Z) >> 32)))
#pragma unroll
    for (int nn = 0; nn < 4; nn++) {
        float4 acc = (nn == 0) ? UNPK(a0x, a0z) : (nn == 1) ? UNPK(a1x, a1z)
                   : (nn == 2) ? UNPK(a2x, a2z) : UNPK(a3x, a3z);
        int n = n0 + nn;
        if (n < N_NODES) {
            uint2 pk;
            half2 p01 = __float22half2_rn(make_float2(acc.x, acc.y));
            half2 p23 = __float22half2_rn(make_float2(acc.z, acc.w));
            pk.x = *reinterpret_cast<unsigned*>(&p01);
            pk.y = *reinterpret_cast<unsigned*>(&p23);
            Wh2[(size_t)n * 32 + lane] = pk;
            // fused k1b: per-node attention scalars
            float ps = acc.x * asx + acc.y * asy + acc.z * asz + acc.w * asw;
            float pd = acc.x * adx + acc.y * ady + acc.z * adz + acc.w * adw;
            ps += __shfl_xor_sync(0xffffffffu, ps, 1); pd += __shfl_xor_sync(0xffffffffu, pd, 1);
            ps += __shfl_xor_sync(0xffffffffu, ps, 2); pd += __shfl_xor_sync(0xffffffffu, pd, 2);
            ps += __shfl_xor_sync(0xffffffffu, ps, 4); pd += __shfl_xor_sync(0xffffffffu, pd, 4);
            if ((lane & 7) == 0) {
                int head = lane >> 3;
                g_s[(size_t)n * 8 + head]     = ps;
                g_s[(size_t)n * 8 + 4 + head] = pd;
            }
        }
    }
#undef UNPK
}

// ---------------- K2: edge logits (thread per edge, 4 heads in registers) -------
// 256 edges/block; k streamed in 4 chunks of 8 float4 through smem.
__global__ __launch_bounds__(256) void k2_logits(const float4* __restrict__ ef4,
                                                 const int* __restrict__ ei) {
    __shared__ float4 xs[8][257];        // [kc][edge], stride 257*16B -> bank step 4
    __shared__ float4 ves[128];          // [h][kc] as float4
    __shared__ unsigned bmax[4];
    int tid = threadIdx.x;
    if (tid < 128) ves[tid] = reinterpret_cast<const float4*>(g_ve)[tid];
    if (tid < 4) bmax[tid] = 0u;

    int ebase = blockIdx.x * 256;        // grid = 2500, exact
    int eld = tid >> 3, kcld = tid & 7;

    float a0 = 0.f, a1 = 0.f, a2 = 0.f, a3 = 0.f;
#pragma unroll
    for (int c = 0; c < 4; c++) {
        __syncthreads();
#pragma unroll
        for (int j = 0; j < 8; j++) {
            int e = eld + 32 * j;
            xs[kcld][e] = ef4[(size_t)(ebase + e) * 32 + c * 8 + kcld];
        }
        __syncthreads();
#pragma unroll
        for (int kc = 0; kc < 8; kc++) {
            float4 xv = xs[kc][tid];
            float4 v0 = ves[0 * 32 + c * 8 + kc];
            float4 v1 = ves[1 * 32 + c * 8 + kc];
            float4 v2 = ves[2 * 32 + c * 8 + kc];
            float4 v3 = ves[3 * 32 + c * 8 + kc];
            a0 = fmaf(xv.x, v0.x, a0); a0 = fmaf(xv.y, v0.y, a0);
            a0 = fmaf(xv.z, v0.z, a0); a0 = fmaf(xv.w, v0.w, a0);
            a1 = fmaf(xv.x, v1.x, a1); a1 = fmaf(xv.y, v1.y, a1);
            a1 = fmaf(xv.z, v1.z, a1); a1 = fmaf(xv.w, v1.w, a1);
            a2 = fmaf(xv.x, v2.x, a2); a2 = fmaf(xv.y, v2.y, a2);
            a2 = fmaf(xv.z, v2.z, a2); a2 = fmaf(xv.w, v2.w, a2);
            a3 = fmaf(xv.x, v3.x, a3); a3 = fmaf(xv.y, v3.y, a3);
            a3 = fmaf(xv.z, v3.z, a3); a3 = fmaf(xv.w, v3.w, a3);
        }
    }

    int e = ebase + tid;
    int src = __ldg(&ei[e]);
    int dst = __ldg(&ei[N_EDGES + e]);
    float4 ss = __ldg(reinterpret_cast<const float4*>(g_s) + (size_t)src * 2);
    float4 sd = __ldg(reinterpret_cast<const float4*>(g_s) + (size_t)dst * 2 + 1);
    float4 ev;
    ev.x = a0 + ss.x + sd.x; ev.y = a1 + ss.y + sd.y;
    ev.z = a2 + ss.z + sd.z; ev.w = a3 + ss.w + sd.w;
    ev.x = (ev.x >= 0.f) ? ev.x : ALPHA * ev.x;
    ev.y = (ev.y >= 0.f) ? ev.y : ALPHA * ev.y;
    ev.z = (ev.z >= 0.f) ? ev.z : ALPHA * ev.z;
    ev.w = (ev.w >= 0.f) ? ev.w : ALPHA * ev.w;
    reinterpret_cast<float4*>(g_p)[e] = ev;
    atomicAdd(&g_cnt[dst], 1);           // histogram for CSR

    float m0 = ev.x, m1 = ev.y, m2 = ev.z, m3 = ev.w;
#pragma unroll
    for (int m = 16; m; m >>= 1) {
        m0 = fmaxf(m0, __shfl_xor_sync(0xffffffffu, m0, m));
        m1 = fmaxf(m1, __shfl_xor_sync(0xffffffffu, m1, m));
        m2 = fmaxf(m2, __shfl_xor_sync(0xffffffffu, m2, m));
        m3 = fmaxf(m3, __shfl_xor_sync(0xffffffffu, m3, m));
    }
    if ((tid & 31) == 0) {
        atomicMax(&bmax[0], fenc(m0)); atomicMax(&bmax[1], fenc(m1));
        atomicMax(&bmax[2], fenc(m2)); atomicMax(&bmax[3], fenc(m3));
    }
    __syncthreads();
    if (tid < 4) atomicMax(&g_max[tid], bmax[tid]);
}

// ---------------- scan (3 small kernels) ----------------
__global__ void k_scan1() {
    __shared__ int s[256];
    int t = threadIdx.x;
    int i = blockIdx.x * 256 + t;
    int c = (i < N_NODES) ? g_cnt[i] : 0;
    s[t] = c;
    __syncthreads();
#pragma unroll
    for (int d = 1; d < 256; d <<= 1) {
        int v = (t >= d) ? s[t - d] : 0;
        __syncthreads();
        s[t] += v;
        __syncthreads();
    }
    if (i < N_NODES) g_off[i] = s[t] - c;
    if (t == 255) g_bsum[blockIdx.x] = s[255];
}
__global__ void k_scan2(int nblocks) {
    __shared__ int s[256];
    int t = threadIdx.x;
    int c = (t < nblocks) ? g_bsum[t] : 0;
    s[t] = c;
    __syncthreads();
#pragma unroll
    for (int d = 1; d < 256; d <<= 1) {
        int v = (t >= d) ? s[t - d] : 0;
        __syncthreads();
        s[t] += v;
        __syncthreads();
    }
    if (t < nblocks) g_bsum[t] = s[t] - c;   // exclusive
}
__global__ void k_scan3() {
    int i = blockIdx.x * 256 + threadIdx.x;
    if (i < N_NODES) {
        int v = g_off[i] + g_bsum[blockIdx.x];
        g_off[i] = v;
        g_cnt[i] = v;                        // becomes fill cursor
    }
}

// ---------------- K3: exp(e-max) + sums + CSR fill ----------------
__global__ __launch_bounds__(256) void k3_exp_fill(const int* __restrict__ ei) {
    __shared__ float bs[4];
    int tid = threadIdx.x;
    if (tid < 4) bs[tid] = 0.0f;
    __syncthreads();
    int e = blockIdx.x * 256 + tid;          // grid 2500, exact
    int lane = tid & 31;
    float m0 = fdec(g_max[0]), m1 = fdec(g_max[1]), m2 = fdec(g_max[2]), m3 = fdec(g_max[3]);
    float4 v = reinterpret_cast<float4*>(g_p)[e];
    v.x = __expf(v.x - m0); v.y = __expf(v.y - m1);
    v.z = __expf(v.z - m2); v.w = __expf(v.w - m3);
    reinterpret_cast<float4*>(g_p)[e] = v;
    int dst = __ldg(&ei[N_EDGES + e]);
    int idx = atomicAdd(&g_cnt[dst], 1);
    g_list[idx] = e;
    float4 r = v;
#pragma unroll
    for (int m = 16; m; m >>= 1) {
        r.x += __shfl_xor_sync(0xffffffffu, r.x, m);
        r.y += __shfl_xor_sync(0xffffffffu, r.y, m);
        r.z += __shfl_xor_sync(0xffffffffu, r.z, m);
        r.w += __shfl_xor_sync(0xffffffffu, r.w, m);
    }
    if (lane == 0) {
        atomicAdd(&bs[0], r.x); atomicAdd(&bs[1], r.y);
        atomicAdd(&bs[2], r.z); atomicAdd(&bs[3], r.w);
    }
    __syncthreads();
    if (tid < 4) atomicAdd(&g_sum[tid], bs[tid]);
}

// ---------------- K4: warp-per-dst gather (fp16 Wh) + fused ReLU ----------------
__global__ __launch_bounds__(256) void k4_gather(const int* __restrict__ ei,
                                                 float* __restrict__ out) {
    int node = (blockIdx.x * 256 + threadIdx.x) >> 5;
    int lane = threadIdx.x & 31;
    if (node >= N_NODES) return;
    int head = lane >> 3;
    float inv = __fdividef(1.0f, __ldg(&g_sum[head]));
    int beg = __ldg(&g_off[node]);
    int end = __ldg(&g_cnt[node]);           // cursor == row end after fill
    const uint2* Wh2 = reinterpret_cast<const uint2*>(g_Wh_h);
    const float4* p4 = reinterpret_cast<const float4*>(g_p);
    float4 acc = {0.f, 0.f, 0.f, 0.f};
    int i = beg;
    for (; i + 2 <= end; i += 2) {
        int ea = __ldg(&g_list[i]);
        int eb = __ldg(&g_list[i + 1]);
        int sa = __ldg(&ei[ea]);
        int sb = __ldg(&ei[eb]);
        float4 pa = __ldg(&p4[ea]);
        float4 pb = __ldg(&p4[eb]);
        uint2 wa = __ldg(&Wh2[(size_t)sa * 32 + lane]);
        uint2 wb = __ldg(&Wh2[(size_t)sb * 32 + lane]);
        float sca = (head == 0 ? pa.x : head == 1 ? pa.y : head == 2 ? pa.z : pa.w) * inv;
        float scb = (head == 0 ? pb.x : head == 1 ? pb.y : head == 2 ? pb.z : pb.w) * inv;
        float2 fa01 = __half22float2(*reinterpret_cast<half2*>(&wa.x));
        float2 fa23 = __half22float2(*reinterpret_cast<half2*>(&wa.y));
        float2 fb01 = __half22float2(*reinterpret_cast<half2*>(&wb.x));
        float2 fb23 = __half22float2(*reinterpret_cast<half2*>(&wb.y));
        acc.x = fmaf(sca, fa01.x, acc.x); acc.y = fmaf(sca, fa01.y, acc.y);
        acc.z = fmaf(sca, fa23.x, acc.z); acc.w = fmaf(sca, fa23.y, acc.w);
        acc.x = fmaf(scb, fb01.x, acc.x); acc.y = fmaf(scb, fb01.y, acc.y);
        acc.z = fmaf(scb, fb23.x, acc.z); acc.w = fmaf(scb, fb23.y, acc.w);
    }
    if (i < end) {
        int ea = __ldg(&g_list[i]);
        int sa = __ldg(&ei[ea]);
        float4 pa = __ldg(&p4[ea]);
        uint2 wa = __ldg(&Wh2[(size_t)sa * 32 + lane]);
        float sca = (head == 0 ? pa.x : head == 1 ? pa.y : head == 2 ? pa.z : pa.w) * inv;
        float2 fa01 = __half22float2(*reinterpret_cast<half2*>(&wa.x));
        float2 fa23 = __half22float2(*reinterpret_cast<half2*>(&wa.y));
        acc.x = fmaf(sca, fa01.x, acc.x); acc.y = fmaf(sca, fa01.y, acc.y);
        acc.z = fmaf(sca, fa23.x, acc.z); acc.w = fmaf(sca, fa23.y, acc.w);
    }
    acc.x = fmaxf(acc.x, 0.f); acc.y = fmaxf(acc.y, 0.f);
    acc.z = fmaxf(acc.z, 0.f); acc.w = fmaxf(acc.w, 0.f);
    reinterpret_cast<float4*>(out)[(size_t)node * 32 + lane] = acc;
}

extern "C" void kernel_launch(void* const* d_in, const int* in_sizes, int n_in,
                              void* d_out, int out_size) {
    const int*   ei     = (const int*)d_in[0];   // [2,E]
    const float* h      = (const float*)d_in[1]; // [N,128]
    const float* ef     = (const float*)d_in[2]; // [E,128]
    const float* W      = (const float*)d_in[3]; // [128,128]
    const float* We     = (const float*)d_in[4]; // [128,128]
    const float* a_src  = (const float*)d_in[5]; // [1,4,32]
    const float* a_dst  = (const float*)d_in[6];
    const float* a_edge = (const float*)d_in[7];
    float* out = (float*)d_out;

    const int scan_blocks = (N_NODES + 255) / 256;   // 196

    k_init<<<scan_blocks, 256>>>(We, a_edge);
    k1_gemm<<<(N_NODES + 31) / 32, 256>>>(h, W, a_src, a_dst);
    k2_logits<<<N_EDGES / 256, 256>>>((const float4*)ef, ei);
    k_scan1<<<scan_blocks, 256>>>();
    k_scan2<<<1, 256>>>(scan_blocks);
    k_scan3<<<scan_blocks, 256>>>();
    k3_exp_fill<<<N_EDGES / 256, 256>>>(ei);
    k4_gather<<<(N_NODES * 32 + 255) / 256, 256>>>(ei, out);
}